// round 16
// baseline (speedup 1.0000x reference)
#include <cuda_runtime.h>
#include <cuda_fp16.h>
#include <cstdint>

// Problem constants
#define B_    2
#define S_    2048
#define D_    1024
#define FF_   4096
#define H_    16
#define DH_   64
#define L_    4
#define MTOK  (B_ * S_)      // 4096 tokens
#define QKV_N (3 * D_)       // 3072

// ---------------------------------------------------------------------------
// Scratch (static device globals; no runtime allocation)
// ---------------------------------------------------------------------------
__device__ float  g_x   [MTOK * D_];          // running hidden (fp32)
__device__ __half g_xh  [MTOK * D_];          // fp16 hidden
__device__ __half g_qkv [MTOK * QKV_N];       // fused QKV (fp16)
__device__ __half g_ch  [MTOK * D_];          // attention ctx (fp16)
__device__ float  g_t   [MTOK * D_];          // pre-LN temp
__device__ __half g_ff  [MTOK * FF_];         // FFN hidden (fp16)

// transposed fp16 weights ([N, K] row-major)
__device__ __half g_wqkv[L_ * QKV_N * D_];
__device__ __half g_wp  [L_ * D_ * D_];
__device__ __half g_w1  [L_ * FF_ * D_];      // [FF, D]
__device__ __half g_w2  [L_ * D_ * FF_];      // [D, FF]
__device__ float  g_bqkv[L_ * QKV_N];

// ---------------------------------------------------------------------------
// Baseline-PTX helpers (sm_75/80 features only)
// ---------------------------------------------------------------------------
__device__ __forceinline__ uint32_t smem_u32(const void* p) {
    uint32_t a;
    asm("{ .reg .u64 t; cvta.to.shared.u64 t, %1; cvt.u32.u64 %0, t; }"
        : "=r"(a) : "l"(p));
    return a;
}
__device__ __forceinline__ void cp16(uint32_t s, const void* g) {
    asm volatile("cp.async.cg.shared.global [%0], [%1], 16;" :: "r"(s), "l"(g));
}
#define CP_COMMIT() asm volatile("cp.async.commit_group;" ::: "memory")

__device__ __forceinline__ void cp_wait_dyn(int more) {
    if (more) asm volatile("cp.async.wait_group 1;" ::: "memory");
    else      asm volatile("cp.async.wait_group 0;" ::: "memory");
}

__device__ __forceinline__ void ldsm4(uint32_t r[4], uint32_t addr) {
    asm volatile("ldmatrix.sync.aligned.m8n8.x4.shared.b16 {%0,%1,%2,%3}, [%4];"
        : "=r"(r[0]), "=r"(r[1]), "=r"(r[2]), "=r"(r[3]) : "r"(addr));
}
__device__ __forceinline__ void ldsm4t(uint32_t r[4], uint32_t addr) {
    asm volatile("ldmatrix.sync.aligned.m8n8.x4.trans.shared.b16 {%0,%1,%2,%3}, [%4];"
        : "=r"(r[0]), "=r"(r[1]), "=r"(r[2]), "=r"(r[3]) : "r"(addr));
}
__device__ __forceinline__ void mma16816(float c[4], const uint32_t a[4],
                                         const uint32_t b[2]) {
    asm volatile(
        "mma.sync.aligned.m16n8k16.row.col.f32.f16.f16.f32 "
        "{%0,%1,%2,%3}, {%4,%5,%6,%7}, {%8,%9}, {%0,%1,%2,%3};"
        : "+f"(c[0]), "+f"(c[1]), "+f"(c[2]), "+f"(c[3])
        : "r"(a[0]), "r"(a[1]), "r"(a[2]), "r"(a[3]),
          "r"(b[0]), "r"(b[1]));
}
__device__ __forceinline__ uint32_t pack_hf2(float a, float b) {
    __half2 t = __halves2half2(__float2half_rn(a), __float2half_rn(b));
    return reinterpret_cast<uint32_t&>(t);
}

// ---------------------------------------------------------------------------
// fp16 1-pass GEMM:  C[M,N] = A[M,K] @ B[N,K]^T + bias (+residual) (+relu)
// Block 128x128, 4 warps (2x2 -> warp tile 64x64), 128 threads.
// K-stage 64, 3-stage cp.async smem ring + single __syncthreads/stage, and
// EXPLICIT per-kk fragment double-buffering: fragments for kk+1 are loaded
// (LSU pipe) before the 32 HMMA of kk issue (tensor pipe), overlapping the
// two pipes instead of serializing them. Regs: 128 acc + 64 frag + addr.
// Stage 32KB; ring 96KB; 2 CTAs/SM.
// ---------------------------------------------------------------------------
#define GSTAGE  32768
#define GSMEM   (3 * GSTAGE)   // 98304

__device__ __forceinline__ void gemm_load_stage(
    uint32_t sbase, const __half* __restrict__ Ah,
    const __half* __restrict__ Bh,
    int m0, int n0, int K, int k0, int tid)
{
    #pragma unroll
    for (int i = 0; i < 16; i++) {
        const int task = tid + i * 128;          // 2048 tasks, 128 threads
        const int arr = task >> 10;              // 0=A, 1=B
        const int idx = task & 1023;
        const int r = idx >> 3, ch = idx & 7;
        const uint32_t dst = sbase + arr * 16384 + r * 128
                           + (uint32_t)((ch ^ (r & 7)) << 4);
        const __half* src = arr
            ? Bh + (size_t)(n0 + r) * K + k0 + ch * 8
            : Ah + (size_t)(m0 + r) * K + k0 + ch * 8;
        cp16(dst, src);
    }
}

__global__ void __launch_bounds__(128, 2) gemm_mma(
    const __half* __restrict__ Ah, const __half* __restrict__ Bh,
    const float* __restrict__ bias, const float* __restrict__ Rsd,
    float* __restrict__ Cf, __half* __restrict__ Ch,
    int K, int N, int relu)
{
    extern __shared__ char sm[];
    const uint32_t smb = smem_u32(sm);
    const int tid = threadIdx.x;
    const int wid = tid >> 5, lane = tid & 31;
    const int wm = wid >> 1, wn = wid & 1;          // warp grid 2x2
    const int lq = lane >> 2, lr = lane & 3;
    const int m0 = blockIdx.y * 128, n0 = blockIdx.x * 128;

    float acc[4][8][4];
    #pragma unroll
    for (int i = 0; i < 4; i++)
        #pragma unroll
        for (int j = 0; j < 8; j++)
            #pragma unroll
            for (int k = 0; k < 4; k++) acc[i][j][k] = 0.0f;

    const int NS = K / 64;    // 16 (K=1024) or 64 (K=4096)

    gemm_load_stage(smb,          Ah, Bh, m0, n0, K, 0,  tid);
    CP_COMMIT();
    gemm_load_stage(smb + GSTAGE, Ah, Bh, m0, n0, K, 64, tid);
    CP_COMMIT();

    const int a_rl = ((lane >> 3) & 1) * 8 + (lane & 7);  // A row grp
    const int a_cg = (lane >> 4) & 1;                     // A k-chunk
    const int b_rl = ((lane >> 4) & 1) * 8 + (lane & 7);  // B row grp
    const int b_cg = (lane >> 3) & 1;                     // B k-chunk

    // Pre-computed ldsm base addresses (stage-relative), constant per thread
    uint32_t a_off[4], b_off[4];
    #pragma unroll
    for (int mt = 0; mt < 4; mt++) {
        const int row = wm * 64 + mt * 16 + a_rl;
        a_off[mt] = (uint32_t)(row * 128) + (uint32_t)((a_cg ^ (row & 7)) << 4);
    }
    #pragma unroll
    for (int u = 0; u < 4; u++) {
        const int j = wn * 64 + u * 16 + b_rl;
        b_off[u] = (uint32_t)(j * 128) + (uint32_t)((b_cg ^ (j & 7)) << 4);
    }
    // XOR deltas to move the swizzled chunk index by +2k (chunk bits 1..2
    // live in address bits 5..6 of the 16B-slot field, i.e. <<4)
    // addr(kk) = base ^ (swz(a_cg + 2*kk) ^ swz(a_cg)) ... since XOR swizzle
    // is linear, chunk c^row-bits: addr(kk) = base ^ ((2*kk) << 4).

    uint32_t ah[2][4][4], bh[2][8][2];

    #define LOAD_FRAGS(buf, kkv)                                            \
        do {                                                                \
            const uint32_t kx = (uint32_t)((2 * (kkv)) << 4);               \
            _Pragma("unroll")                                               \
            for (int mt = 0; mt < 4; mt++)                                  \
                ldsm4(ah[buf][mt], sA + (a_off[mt] ^ kx));                  \
            _Pragma("unroll")                                               \
            for (int u = 0; u < 4; u++) {                                   \
                uint32_t t4[4];                                             \
                ldsm4(t4, sB + (b_off[u] ^ kx));                            \
                bh[buf][2*u][0]   = t4[0]; bh[buf][2*u][1]   = t4[1];       \
                bh[buf][2*u+1][0] = t4[2]; bh[buf][2*u+1][1] = t4[3];       \
            }                                                               \
        } while (0)

    int bufc = 0;                  // s % 3
    int bufn = 2;                  // (s+2) % 3
    for (int s = 0; s < NS; s++) {
        cp_wait_dyn(s + 1 < NS);
        __syncthreads();
        if (s + 2 < NS) {
            gemm_load_stage(smb + bufn * GSTAGE,
                            Ah, Bh, m0, n0, K, (s + 2) * 64, tid);
            CP_COMMIT();
        }

        const uint32_t sA = smb + bufc * GSTAGE;
        const uint32_t sB = sA + 16384;
        bufc = (bufc == 2) ? 0 : bufc + 1;
        bufn = (bufn == 2) ? 0 : bufn + 1;

        LOAD_FRAGS(0, 0);
        #pragma unroll
        for (int kk = 0; kk < 4; kk++) {
            const int cur = kk & 1;
            if (kk < 3) LOAD_FRAGS(cur ^ 1, kk + 1);
            #pragma unroll
            for (int mt = 0; mt < 4; mt++)
                #pragma unroll
                for (int nt = 0; nt < 8; nt++)
                    mma16816(acc[mt][nt], ah[cur][mt], bh[cur][nt]);
        }
    }
    #undef LOAD_FRAGS

    // Epilogue (fragment: c0,c1 at (lq, 2lr), c2,c3 at (lq+8, 2lr))
    const int row0 = m0 + wm * 64;
    const int col0 = n0 + wn * 64;
    #pragma unroll
    for (int mt = 0; mt < 4; mt++) {
        #pragma unroll
        for (int nt = 0; nt < 8; nt++) {
            const int c = col0 + nt * 8 + lr * 2;
            const float b0 = bias[c], b1 = bias[c + 1];
            #pragma unroll
            for (int h = 0; h < 2; h++) {
                const int r = row0 + mt * 16 + lq + h * 8;
                float v0 = acc[mt][nt][2 * h]     + b0;
                float v1 = acc[mt][nt][2 * h + 1] + b1;
                const size_t o = (size_t)r * N + c;
                if (Rsd) {
                    const float2 rv = *(const float2*)(Rsd + o);
                    v0 += rv.x; v1 += rv.y;
                }
                if (relu) { v0 = fmaxf(v0, 0.0f); v1 = fmaxf(v1, 0.0f); }
                if (Cf) *(float2*)(Cf + o) = make_float2(v0, v1);
                if (Ch) *(uint32_t*)(Ch + o) = pack_hf2(v0, v1);
            }
        }
    }
}

// ---------------------------------------------------------------------------
// FA2-style attention, pure fp16 1-pass on QK^T and PV.
// Block 64 q-rows, 4 warps, Bc=64, DH=64 (rows naturally 128B).
// 3-stage KV ring, single __syncthreads per key tile.
// smem: Q 8KB + 3 stages x (K 8KB + V 8KB) = 56KB -> 3 CTAs/SM.
// Swizzle ch^(r&7). Grid: (S/64, H, B), 128 threads.
// ---------------------------------------------------------------------------
#define A_STG  8192
#define A_SSZ  16384
#define ATTN_SMEM (A_STG + 3 * A_SSZ)   // 57344

__device__ __forceinline__ void attn_load_kv(
    uint32_t sbase, const __half* __restrict__ QKV,
    size_t krow0, int hcol, int tid)
{
    // 2 arrays (K, V) x 64 rows x 8 chunks = 1024 tasks, 128 threads
    #pragma unroll
    for (int i = 0; i < 8; i++) {
        const int task = tid + i * 128;
        const int arr = task >> 9;               // 0 = K, 1 = V
        const int r = (task >> 3) & 63;
        const int ch = task & 7;
        const uint32_t dst = sbase + arr * 8192 + r * 128
                           + (uint32_t)((ch ^ (r & 7)) << 4);
        const int col = (arr ? 2 * D_ : D_) + hcol + ch * 8;
        cp16(dst, QKV + (krow0 + r) * QKV_N + col);
    }
}

__global__ void __launch_bounds__(128, 3) attn_mma(
    const __half* __restrict__ QKV, __half* __restrict__ Ch)
{
    extern __shared__ char sm[];
    const uint32_t smb = smem_u32(sm);
    const int tid = threadIdx.x;
    const int w = tid >> 5, lane = tid & 31;
    const int lq = lane >> 2, lr = lane & 3;
    const int qt = blockIdx.x, h = blockIdx.y, b = blockIdx.z;
    const size_t qrow0 = (size_t)b * S_ + qt * 64;
    const size_t krowb = (size_t)b * S_;
    const int hcol = h * DH_;

    // ---- load Q tile (512 tasks) + KV stages 0,1
    #pragma unroll
    for (int i = 0; i < 4; i++) {
        const int task = tid + i * 128;
        const int r = task >> 3, ch = task & 7;
        const uint32_t dst = smb + r * 128 + (uint32_t)((ch ^ (r & 7)) << 4);
        cp16(dst, QKV + (qrow0 + r) * QKV_N + hcol + ch * 8);
    }
    attn_load_kv(smb + A_STG, QKV, krowb, hcol, tid);
    CP_COMMIT();
    attn_load_kv(smb + A_STG + A_SSZ, QKV, krowb + 64, hcol, tid);
    CP_COMMIT();

    float m0 = -1e30f, m1 = -1e30f, l0 = 0.0f, l1 = 0.0f;
    float oacc[8][4];
    #pragma unroll
    for (int t = 0; t < 8; t++)
        #pragma unroll
        for (int i = 0; i < 4; i++) oacc[t][i] = 0.0f;

    uint32_t qh[4][4];

    const int a_rl = ((lane >> 3) & 1) * 8 + (lane & 7);
    const int a_cg = (lane >> 4) & 1;
    const int b_rl = ((lane >> 4) & 1) * 8 + (lane & 7);
    const int b_cg = (lane >> 3) & 1;

    const int NT = S_ / 64;   // 32 key tiles
    int bufc = 0, bufn = 2;
    for (int j = 0; j < NT; j++) {
        cp_wait_dyn(j + 1 < NT);
        __syncthreads();
        if (j + 2 < NT) {
            attn_load_kv(smb + A_STG + bufn * A_SSZ,
                         QKV, krowb + (size_t)(j + 2) * 64, hcol, tid);
            CP_COMMIT();
        }

        if (j == 0) {
            // load Q fragments once; fold in softmax scale 1/8 (exact)
            const __half2 s2 = __float2half2_rn(0.125f);
            #pragma unroll
            for (int kk = 0; kk < 4; kk++) {
                const int row = w * 16 + a_rl;
                const int chh = a_cg + 2 * kk;
                ldsm4(qh[kk], smb + row * 128 + ((chh ^ (row & 7)) << 4));
                #pragma unroll
                for (int i = 0; i < 4; i++) {
                    __half2 vh = reinterpret_cast<__half2&>(qh[kk][i]);
                    vh = __hmul2(vh, s2);
                    qh[kk][i] = reinterpret_cast<uint32_t&>(vh);
                }
            }
        }

        const uint32_t sK = smb + A_STG + bufc * A_SSZ;
        const uint32_t sV = sK + 8192;
        bufc = (bufc == 2) ? 0 : bufc + 1;
        bufn = (bufn == 2) ? 0 : bufn + 1;

        // ---- S = Q @ K^T (1 pass): 16x64 per warp
        float sacc[8][4];
        #pragma unroll
        for (int t = 0; t < 8; t++)
            #pragma unroll
            for (int i = 0; i < 4; i++) sacc[t][i] = 0.0f;

        #pragma unroll
        for (int kk = 0; kk < 4; kk++) {
            uint32_t kh[8][2];
            #pragma unroll
            for (int u = 0; u < 4; u++) {
                const int row = u * 16 + b_rl;      // key index
                const int chh = 2 * kk + b_cg;      // d chunk
                uint32_t t4[4];
                ldsm4(t4, sK + row * 128 + ((chh ^ (row & 7)) << 4));
                kh[2*u][0] = t4[0]; kh[2*u][1] = t4[1];
                kh[2*u+1][0] = t4[2]; kh[2*u+1][1] = t4[3];
            }
            #pragma unroll
            for (int t = 0; t < 8; t++)
                mma16816(sacc[t], qh[kk], kh[t]);
        }

        // ---- online softmax (rows lq and lq+8)
        float mx0 = -1e30f, mx1 = -1e30f;
        #pragma unroll
        for (int t = 0; t < 8; t++) {
            mx0 = fmaxf(mx0, fmaxf(sacc[t][0], sacc[t][1]));
            mx1 = fmaxf(mx1, fmaxf(sacc[t][2], sacc[t][3]));
        }
        mx0 = fmaxf(mx0, __shfl_xor_sync(0xffffffffu, mx0, 1));
        mx0 = fmaxf(mx0, __shfl_xor_sync(0xffffffffu, mx0, 2));
        mx1 = fmaxf(mx1, __shfl_xor_sync(0xffffffffu, mx1, 1));
        mx1 = fmaxf(mx1, __shfl_xor_sync(0xffffffffu, mx1, 2));
        const float nm0 = fmaxf(m0, mx0), nm1 = fmaxf(m1, mx1);
        const float al0 = __expf(m0 - nm0), al1 = __expf(m1 - nm1);
        m0 = nm0; m1 = nm1;

        float ps0 = 0.0f, ps1 = 0.0f;
        #pragma unroll
        for (int t = 0; t < 8; t++) {
            sacc[t][0] = __expf(sacc[t][0] - m0);
            sacc[t][1] = __expf(sacc[t][1] - m0);
            sacc[t][2] = __expf(sacc[t][2] - m1);
            sacc[t][3] = __expf(sacc[t][3] - m1);
            ps0 += sacc[t][0] + sacc[t][1];
            ps1 += sacc[t][2] + sacc[t][3];
        }
        ps0 += __shfl_xor_sync(0xffffffffu, ps0, 1);
        ps0 += __shfl_xor_sync(0xffffffffu, ps0, 2);
        ps1 += __shfl_xor_sync(0xffffffffu, ps1, 1);
        ps1 += __shfl_xor_sync(0xffffffffu, ps1, 2);
        l0 = l0 * al0 + ps0;
        l1 = l1 * al1 + ps1;

        #pragma unroll
        for (int t = 0; t < 8; t++) {
            oacc[t][0] *= al0; oacc[t][1] *= al0;
            oacc[t][2] *= al1; oacc[t][3] *= al1;
        }

        // ---- P -> fp16 A-fragments (C-layout -> A-layout identity)
        uint32_t ph[4][4];
        #pragma unroll
        for (int kk = 0; kk < 4; kk++) {
            const int t0 = 2 * kk, t1 = 2 * kk + 1;
            ph[kk][0] = pack_hf2(sacc[t0][0], sacc[t0][1]);
            ph[kk][1] = pack_hf2(sacc[t0][2], sacc[t0][3]);
            ph[kk][2] = pack_hf2(sacc[t1][0], sacc[t1][1]);
            ph[kk][3] = pack_hf2(sacc[t1][2], sacc[t1][3]);
        }

        // ---- O += P @ V (1 pass); V^T via ldmatrix.trans
        #pragma unroll
        for (int kk = 0; kk < 4; kk++) {           // key window 16*kk
            uint32_t vh[8][2];
            #pragma unroll
            for (int u = 0; u < 4; u++) {
                const int row = 16 * kk + a_rl;    // key row
                const int chh = 2 * u + a_cg;      // d chunk
                uint32_t t4[4];
                ldsm4t(t4, sV + row * 128 + ((chh ^ (row & 7)) << 4));
                vh[2*u][0] = t4[0]; vh[2*u][1] = t4[1];
                vh[2*u+1][0] = t4[2]; vh[2*u+1][1] = t4[3];
            }
            #pragma unroll
            for (int t = 0; t < 8; t++)
                mma16816(oacc[t], ph[kk], vh[t]);
        }
    }

    // ---- epilogue: O /= l, write ctx fp16
    const float i0 = 1.0f / l0, i1 = 1.0f / l1;
    const size_t r0g = qrow0 + w * 16 + lq;
    #pragma unroll
    for (int t = 0; t < 8; t++) {
        const int col = hcol + t * 8 + 2 * lr;
        *(uint32_t*)(Ch + r0g * D_ + col) =
            pack_hf2(oacc[t][0] * i0, oacc[t][1] * i0);
        *(uint32_t*)(Ch + (r0g + 8) * D_ + col) =
            pack_hf2(oacc[t][2] * i1, oacc[t][3] * i1);
    }
}

// ---------------------------------------------------------------------------
// Fused preprocessing: ALL weight transposes (fp32 [K,N] -> fp16 [N,K]),
// QKV bias concat, and hidden-state fp32 copy + fp16 cast — ONE launch.
// ---------------------------------------------------------------------------
#define PREP_BLOCKS 65584

__global__ void __launch_bounds__(256) prep_all(
    const float* __restrict__ hs,
    const float* __restrict__ Wq, const float* __restrict__ Wk,
    const float* __restrict__ Wv, const float* __restrict__ Wp,
    const float* __restrict__ W1, const float* __restrict__ W2,
    const float* __restrict__ bq, const float* __restrict__ bk,
    const float* __restrict__ bv,
    __half* __restrict__ wqkv, __half* __restrict__ wpw,
    __half* __restrict__ w1w, __half* __restrict__ w2w,
    float* __restrict__ bqkv, float* __restrict__ x,
    __half* __restrict__ xh)
{
    const int bid = blockIdx.x;

    if (bid >= 49200) {                         // hidden copy + cast
        const int i = (bid - 49200) * 256 + threadIdx.x;
        const float v = hs[i];
        x[i] = v;
        xh[i] = __float2half_rn(v);
        return;
    }
    if (bid >= 49152) {                         // bias concat
        const int i = (bid - 49152) * 256 + threadIdx.x;
        const int l = i / QKV_N, j = i % QKV_N;
        float v;
        if (j < D_)            v = bq[l * D_ + j];
        else if (j < 2 * D_)   v = bk[l * D_ + j - D_];
        else                   v = bv[l * D_ + j - 2 * D_];
        bqkv[i] = v;
        return;
    }

    // ---- weight transpose tile
    const float* src; __half* dst; int K, N;
    size_t in_ls, out_ls;
    int local;
    if (bid < 16384) {
        const int g = bid >> 12;                // 0..3
        local = bid & 4095;
        K = D_; N = D_; in_ls = (size_t)D_ * D_;
        if (g == 0)      { src = Wq; dst = wqkv;                     out_ls = (size_t)QKV_N * D_; }
        else if (g == 1) { src = Wk; dst = wqkv + (size_t)D_ * D_;   out_ls = (size_t)QKV_N * D_; }
        else if (g == 2) { src = Wv; dst = wqkv + (size_t)2*D_ * D_; out_ls = (size_t)QKV_N * D_; }
        else             { src = Wp; dst = wpw;                      out_ls = (size_t)D_ * D_; }
    } else if (bid < 32768) {
        local = bid - 16384;
        src = W1; dst = w1w; K = D_; N = FF_;
        in_ls = (size_t)D_ * FF_; out_ls = (size_t)FF_ * D_;
    } else {
        local = bid - 32768;
        src = W2; dst = w2w; K = FF_; N = D_;
        in_ls = (size_t)FF_ * D_; out_ls = (size_t)D_ * FF_;
    }
    const int ntn = N / 32;
    const int tpl = ntn * (K / 32);
    const int l = local / tpl, rem = local % tpl;
    const int n0 = (rem % ntn) * 32, k0 = (rem / ntn) * 32;
    const float* Wl = src + (size_t)l * in_ls;
    __half* Ol = dst + (size_t)l * out_ls;

    __shared__ float t[32][33];
    const int tx = threadIdx.x & 31, ty = threadIdx.x >> 5;
    #pragma unroll
    for (int i = 0; i < 32; i += 8)
        t[ty + i][tx] = Wl[(size_t)(k0 + ty + i) * N + n0 + tx];
    __syncthreads();
    #pragma unroll
    for (int i = 0; i < 32; i += 8)
        Ol[(size_t)(n0 + ty + i) * K + k0 + tx] = __float2half_rn(t[tx][ty + i]);
}

// ---------------------------------------------------------------------------
// LayerNorm over last dim (D=1024); fused fp32 + optional fp16 output.
// ---------------------------------------------------------------------------
__inline__ __device__ float warpSum(float v) {
    #pragma unroll
    for (int o = 16; o > 0; o >>= 1) v += __shfl_xor_sync(0xffffffffu, v, o);
    return v;
}

__global__ void __launch_bounds__(256) ln_kernel(
    const float* __restrict__ in, const float* __restrict__ gamma,
    const float* __restrict__ beta, float* __restrict__ out,
    __half* __restrict__ oh)
{
    const size_t row = blockIdx.x;
    const float4 val = ((const float4*)(in + row * D_))[threadIdx.x];

    float s  = val.x + val.y + val.z + val.w;
    float sq = val.x * val.x + val.y * val.y + val.z * val.z + val.w * val.w;

    __shared__ float ssum[8], ssq[8];
    s  = warpSum(s);
    sq = warpSum(sq);
    const int wid = threadIdx.x >> 5, lane = threadIdx.x & 31;
    if (lane == 0) { ssum[wid] = s; ssq[wid] = sq; }
    __syncthreads();
    s = 0.f; sq = 0.f;
    #pragma unroll
    for (int i = 0; i < 8; i++) { s += ssum[i]; sq += ssq[i]; }

    const float mean = s * (1.0f / D_);
    const float var  = sq * (1.0f / D_) - mean * mean;
    const float rstd = rsqrtf(var + 1e-6f);

    const int c = threadIdx.x << 2;
    const float4 gv = *(const float4*)(gamma + c);
    const float4 bb = *(const float4*)(beta + c);
    float4 o;
    o.x = (val.x - mean) * rstd * gv.x + bb.x;
    o.y = (val.y - mean) * rstd * gv.y + bb.y;
    o.z = (val.z - mean) * rstd * gv.z + bb.z;
    o.w = (val.w - mean) * rstd * gv.w + bb.w;
    ((float4*)(out + row * D_))[threadIdx.x] = o;

    if (oh) {
        *(uint2*)(oh + row * D_ + c) =
            make_uint2(pack_hf2(o.x, o.y), pack_hf2(o.z, o.w));
    }
}

// ---------------------------------------------------------------------------
// Launch
// ---------------------------------------------------------------------------
extern "C" void kernel_launch(void* const* d_in, const int* in_sizes, int n_in,
                              void* d_out, int out_size)
{
    (void)in_sizes; (void)n_in; (void)out_size;

    const float* hs  = (const float*)d_in[0];
    const float* Wq  = (const float*)d_in[1];
    const float* bq  = (const float*)d_in[2];
    const float* Wk  = (const float*)d_in[3];
    const float* bk  = (const float*)d_in[4];
    const float* Wv  = (const float*)d_in[5];
    const float* bv  = (const float*)d_in[6];
    const float* Wp  = (const float*)d_in[7];
    const float* bp  = (const float*)d_in[8];
    const float* g1  = (const float*)d_in[9];
    const float* be1 = (const float*)d_in[10];
    const float* W1  = (const float*)d_in[11];
    const float* b1  = (const float*)d_in[12];
    const float* W2  = (const float*)d_in[13];
    const float* b2  = (const float*)d_in[14];
    const float* g2  = (const float*)d_in[15];
    const float* be2 = (const float*)d_in[16];

    float *x, *t, *bqkv;
    __half *xh, *qkv, *ch, *ff, *wqkv, *wp, *w1, *w2;
    cudaGetSymbolAddress((void**)&x,    g_x);
    cudaGetSymbolAddress((void**)&t,    g_t);
    cudaGetSymbolAddress((void**)&bqkv, g_bqkv);
    cudaGetSymbolAddress((void**)&xh,   g_xh);
    cudaGetSymbolAddress((void**)&qkv,  g_qkv);
    cudaGetSymbolAddress((void**)&ch,   g_ch);
    cudaGetSymbolAddress((void**)&ff,   g_ff);
    cudaGetSymbolAddress((void**)&wqkv, g_wqkv);
    cudaGetSymbolAddress((void**)&wp,   g_wp);
    cudaGetSymbolAddress((void**)&w1,   g_w1);
    cudaGetSymbolAddress((void**)&w2,   g_w2);

    cudaFuncSetAttribute(gemm_mma, cudaFuncAttributeMaxDynamicSharedMemorySize,
                         GSMEM);
    cudaFuncSetAttribute(attn_mma, cudaFuncAttributeMaxDynamicSharedMemorySize,
                         ATTN_SMEM);

    const dim3 tb(256);

    // ---- single fused preprocessing launch ----
    prep_all<<<PREP_BLOCKS, tb>>>(hs, Wq, Wk, Wv, Wp, W1, W2, bq, bk, bv,
                                  wqkv, wp, w1, w2, bqkv, x, xh);

    const dim3 gQKV(QKV_N / 128, MTOK / 128);   // (24, 32)
    const dim3 gD  (D_    / 128, MTOK / 128);   // (8, 32)
    const dim3 gFF (FF_   / 128, MTOK / 128);   // (32, 32)
    const dim3 gA  (S_ / 64, H_, B_);           // (32, 16, 2)
    const dim3 gb(128);                          // GEMM/attn blocks

    for (int l = 0; l < L_; l++) {
        const size_t lDD = (size_t)l * D_ * D_;
        const size_t lDF = (size_t)l * D_ * FF_;

        gemm_mma<<<gQKV, gb, GSMEM>>>(
            xh, wqkv + (size_t)l * QKV_N * D_,
            bqkv + (size_t)l * QKV_N, nullptr, nullptr, qkv,
            D_, QKV_N, 0);

        attn_mma<<<gA, gb, ATTN_SMEM>>>(qkv, ch);

        gemm_mma<<<gD, gb, GSMEM>>>(
            ch, wp + lDD, bp + (size_t)l * D_, x,
            t, nullptr, D_, D_, 0);
        ln_kernel<<<MTOK, tb>>>(t, g1 + (size_t)l * D_, be1 + (size_t)l * D_,
                                x, xh);

        gemm_mma<<<gFF, gb, GSMEM>>>(
            xh, w1 + lDF, b1 + (size_t)l * FF_, nullptr,
            nullptr, ff, D_, FF_, 1);

        gemm_mma<<<gD, gb, GSMEM>>>(
            ff, w2 + lDF, b2 + (size_t)l * D_, x,
            t, nullptr, FF_, D_, 0);

        if (l == L_ - 1) {
            ln_kernel<<<MTOK, tb>>>(t, g2 + (size_t)l * D_, be2 + (size_t)l * D_,
                                    (float*)d_out, nullptr);
        } else {
            ln_kernel<<<MTOK, tb>>>(t, g2 + (size_t)l * D_, be2 + (size_t)l * D_,
                                    x, xh);
        }
    }
}